// round 6
// baseline (speedup 1.0000x reference)
#include <cuda_runtime.h>
#include <math.h>

namespace {
constexpr int BATCH = 128, NNODE = 512, INC = 128, HID = 32, KA = 100, KB = 10, OC = 10;
constexpr int KAP = 128;
constexpr int TOT = BATCH * NNODE;
constexpr int MAXE = BATCH * 8192;
constexpr float EPSV = 1e-15f;

constexpr size_t OFF_DEG    = 0;
constexpr size_t OFF_DFLAT  = OFF_DEG + TOT;
constexpr size_t OFF_LOSSB  = OFF_DFLAT + TOT;
constexpr size_t OFF_XWP    = OFF_LOSSB + BATCH;
constexpr size_t OFF_H      = OFF_XWP   + (size_t)TOT * HID;
constexpr size_t OFF_S1     = OFF_H     + (size_t)TOT * HID;
constexpr size_t OFF_T1     = OFF_S1    + (size_t)TOT * KAP;
constexpr size_t OFF_ADJR1  = OFF_T1    + (size_t)TOT * KAP;
constexpr size_t OFF_SS1    = OFF_ADJR1 + (size_t)BATCH * KAP * KAP;
constexpr size_t OFF_X1     = OFF_SS1   + (size_t)BATCH * KAP * KAP;
constexpr size_t OFF_ADJ1   = OFF_X1    + (size_t)BATCH * KA * HID;
constexpr size_t OFF_DFLAT2 = OFF_ADJ1  + (size_t)BATCH * KA * KA;
constexpr size_t OFF_DUMMY  = OFF_DFLAT2+ (size_t)BATCH * KA;
constexpr size_t OFF_X2     = OFF_DUMMY + (size_t)BATCH * KB;
constexpr size_t OFF_S2     = OFF_X2    + (size_t)BATCH * KA * HID;
constexpr size_t OFF_ADJR2  = OFF_S2    + (size_t)BATCH * KA * KB;
constexpr size_t OFF_SS2    = OFF_ADJR2 + (size_t)BATCH * KB * KB;
constexpr size_t OFF_X3     = OFF_SS2   + (size_t)BATCH * KB * KB;
constexpr size_t OFF_ADJ2   = OFF_X3    + (size_t)BATCH * KB * HID;
constexpr size_t SCRATCH_TOTAL = OFF_ADJ2 + (size_t)BATCH * KB * KB;
}  // namespace

__device__ __align__(16) float g_scratch[SCRATCH_TOTAL];
__device__ __align__(16) int g_cnt_src[TOT];
__device__ __align__(16) int g_cnt_dst[TOT];
__device__ __align__(16) int g_off_src[TOT];
__device__ __align__(16) int g_off_dst[TOT];
__device__ __align__(16) int g_list_src[MAXE];   // dst-locals grouped by src
__device__ __align__(16) int g_list_dst[MAXE];   // src-locals grouped by dst

// ---------------------------------------------------------------------------
// Fused CSR build: one block per graph. smem count -> scan -> smem-cursor fill.
// ---------------------------------------------------------------------------
__global__ __launch_bounds__(512) void build_csr_kernel(
    const int* __restrict__ ei, int E, int eper,
    int* __restrict__ off_src, int* __restrict__ cnt_src,
    int* __restrict__ off_dst, int* __restrict__ cnt_dst,
    int* __restrict__ list_src, int* __restrict__ list_dst,
    float* __restrict__ deg, float* __restrict__ dflat) {
    __shared__ int sc[512], sd[512], sscan[512];
    __shared__ int csrc[512], cdst[512];
    int b = blockIdx.x, tid = threadIdx.x;
    sc[tid] = 0; sd[tid] = 0;
    __syncthreads();
    const int* se = ei + (size_t)b * eper;
    const int* de = ei + E + (size_t)b * eper;
    for (int e = tid; e < eper; e += 512) {
        atomicAdd(&sc[se[e] & 511], 1);
        atomicAdd(&sd[de[e] & 511], 1);
    }
    __syncthreads();
    int vs = sc[tid], vd = sd[tid];
    int g = (b << 9) + tid;
    int base = b * eper;
    dflat[g] = (float)vs;
    deg[g]   = (float)vd;
    cnt_src[g] = vs;
    cnt_dst[g] = vd;
    sscan[tid] = vs; __syncthreads();
    for (int o = 1; o < 512; o <<= 1) {
        int t = (tid >= o) ? sscan[tid - o] : 0;
        __syncthreads(); sscan[tid] += t; __syncthreads();
    }
    int es = base + sscan[tid] - vs;
    off_src[g] = es; csrc[tid] = es;
    __syncthreads();
    sscan[tid] = vd; __syncthreads();
    for (int o = 1; o < 512; o <<= 1) {
        int t = (tid >= o) ? sscan[tid - o] : 0;
        __syncthreads(); sscan[tid] += t; __syncthreads();
    }
    int ed = base + sscan[tid] - vd;
    off_dst[g] = ed; cdst[tid] = ed;
    __syncthreads();
    for (int e = tid; e < eper; e += 512) {
        int s = se[e] & 511, d = de[e] & 511;
        int p = atomicAdd(&csrc[s], 1);
        list_src[p] = d;
        int q = atomicAdd(&cdst[d], 1);
        list_dst[q] = s;
    }
}

// ---------------------------------------------------------------------------
__global__ __launch_bounds__(256) void xwp_kernel(const float* __restrict__ x,
                                                  const float* __restrict__ W,
                                                  const float* __restrict__ deg,
                                                  float* __restrict__ xwp) {
    __shared__ float Ws[INC * HID];
    __shared__ float xs[8][INC];
    int tid = threadIdx.y * 32 + threadIdx.x;
    for (int t = tid; t < INC * HID; t += 256) Ws[t] = W[t];
    int r0 = blockIdx.x * 8;
    for (int t = tid; t < 8 * INC; t += 256) {
        int r = t >> 7, k = t & 127;
        xs[r][k] = x[(size_t)(r0 + r) * INC + k];
    }
    __syncthreads();
    int c = threadIdx.x, r = threadIdx.y;
    float acc = 0.f;
#pragma unroll 8
    for (int k = 0; k < INC; k++) acc += xs[r][k] * Ws[k * HID + c];
    int g = r0 + r;
    float dis = rsqrtf(deg[g] + 1.0f);
    xwp[(size_t)g * HID + c] = dis * acc;
}

// ---------------------------------------------------------------------------
// GCN aggregate, smem-staged gather: block per graph (64 KB tile), warp per
// dest node, conflict-free broadcast LDS.
// ---------------------------------------------------------------------------
__global__ __launch_bounds__(512) void agg_smem_kernel(
    const int* __restrict__ off_dst, const int* __restrict__ cnt_dst,
    const int* __restrict__ list_dst,
    const float* __restrict__ xwp, const float* __restrict__ deg,
    const float* __restrict__ bias, float* __restrict__ h) {
    extern __shared__ float tile[];   // 512*32 floats = 64 KB
    int b = blockIdx.x, tid = threadIdx.x;
    const float4* src = (const float4*)(xwp + ((size_t)b << 14));
    float4* t4 = (float4*)tile;
    for (int i = tid; i < 4096; i += 512) t4[i] = src[i];
    __syncthreads();
    int lane = tid & 31, warp = tid >> 5;
    float bb = bias[lane];
    for (int r = warp; r < 512; r += 16) {
        int node = (b << 9) + r;
        int off = off_dst[node], cnt = cnt_dst[node];
        float acc = 0.f;
        int i = off, end = off + cnt;
        for (; i + 3 < end; i += 4) {
            int s0 = list_dst[i],     s1 = list_dst[i + 1];
            int s2 = list_dst[i + 2], s3 = list_dst[i + 3];
            acc += tile[(s0 << 5) + lane] + tile[(s1 << 5) + lane]
                 + tile[(s2 << 5) + lane] + tile[(s3 << 5) + lane];
        }
        for (; i < end; i++) acc += tile[(list_dst[i] << 5) + lane];
        float dis = rsqrtf(deg[node] + 1.0f);
        float xv = tile[(r << 5) + lane];
        h[((size_t)node << 5) + lane] = fmaxf(dis * (acc + xv) + bb, 0.f);
    }
}

// ---------------------------------------------------------------------------
// T1 = A @ s1, smem-staged: block per (graph, 32-col quarter), 64 KB tile,
// warp per source node.
// ---------------------------------------------------------------------------
__global__ __launch_bounds__(512) void t1_smem_kernel(
    const int* __restrict__ off_src, const int* __restrict__ cnt_src,
    const int* __restrict__ list_src,
    const float* __restrict__ s1p, float* __restrict__ T1) {
    extern __shared__ float tile[];   // 512*32 floats = 64 KB
    int b = blockIdx.y, q = blockIdx.x, tid = threadIdx.x;
    const float4* src = (const float4*)(s1p + (((size_t)b << 9) << 7));
    float4* t4 = (float4*)tile;
    for (int idx = tid; idx < 4096; idx += 512) {
        int row = idx >> 3, c = idx & 7;
        t4[idx] = src[row * 32 + q * 8 + c];
    }
    __syncthreads();
    int lane = tid & 31, warp = tid >> 5;
    int colbase = q << 5;
    for (int r = warp; r < 512; r += 16) {
        int node = (b << 9) + r;
        int off = off_src[node], cnt = cnt_src[node];
        float acc = 0.f;
        int i = off, end = off + cnt;
        for (; i + 3 < end; i += 4) {
            int d0 = list_src[i],     d1 = list_src[i + 1];
            int d2 = list_src[i + 2], d3 = list_src[i + 3];
            acc += tile[(d0 << 5) + lane] + tile[(d1 << 5) + lane]
                 + tile[(d2 << 5) + lane] + tile[(d3 << 5) + lane];
        }
        for (; i < end; i++) acc += tile[(list_src[i] << 5) + lane];
        T1[((size_t)node << 7) + colbase + lane] = acc;
    }
}

// ---------------------------------------------------------------------------
// adjr1 = s1^T T1 (sel=0) / ss1 = s1^T s1 (sel=1). Double-buffered, micro 8x8.
// ---------------------------------------------------------------------------
__global__ __launch_bounds__(256) void atb8_128_kernel(const float* __restrict__ s1p,
                                                       const float* __restrict__ T1,
                                                       float* __restrict__ adjr1,
                                                       float* __restrict__ ss1) {
    __shared__ float As[2][16][128];
    __shared__ float Bs[2][16][128];
    int b = blockIdx.y;
    int sel = blockIdx.x;
    const float* A = s1p + ((size_t)b << 9) * KAP;
    const float* B = (sel ? s1p : T1) + ((size_t)b << 9) * KAP;
    float* C = (sel ? ss1 : adjr1) + (size_t)b * KAP * KAP;
    int tid = threadIdx.x;
    int tx = tid & 15, ty = tid >> 4;
    int lk0 = tid >> 5,         lj0 = (tid & 31) << 2;
    int lk1 = (tid + 256) >> 5, lj1 = ((tid + 256) & 31) << 2;

    float4 pa0, pa1, pb0, pb1;
    pa0 = *(const float4*)(A + lk0 * KAP + lj0);
    pa1 = *(const float4*)(A + lk1 * KAP + lj1);
    pb0 = *(const float4*)(B + lk0 * KAP + lj0);
    pb1 = *(const float4*)(B + lk1 * KAP + lj1);
    *(float4*)&As[0][lk0][lj0] = pa0;
    *(float4*)&As[0][lk1][lj1] = pa1;
    *(float4*)&Bs[0][lk0][lj0] = pb0;
    *(float4*)&Bs[0][lk1][lj1] = pb1;
    __syncthreads();

    float acc[8][8] = {};
    int cur = 0;
    for (int n0 = 0; n0 < NNODE; n0 += 16) {
        int nn = n0 + 16;
        if (nn < NNODE) {
            pa0 = *(const float4*)(A + (nn + lk0) * KAP + lj0);
            pa1 = *(const float4*)(A + (nn + lk1) * KAP + lj1);
            pb0 = *(const float4*)(B + (nn + lk0) * KAP + lj0);
            pb1 = *(const float4*)(B + (nn + lk1) * KAP + lj1);
        }
#pragma unroll
        for (int kk = 0; kk < 16; kk++) {
            float4 a0 = *(float4*)&As[cur][kk][ty * 8];
            float4 a1 = *(float4*)&As[cur][kk][ty * 8 + 4];
            float4 b0 = *(float4*)&Bs[cur][kk][tx * 8];
            float4 b1 = *(float4*)&Bs[cur][kk][tx * 8 + 4];
            float a[8] = {a0.x, a0.y, a0.z, a0.w, a1.x, a1.y, a1.z, a1.w};
            float bv[8] = {b0.x, b0.y, b0.z, b0.w, b1.x, b1.y, b1.z, b1.w};
#pragma unroll
            for (int u = 0; u < 8; u++)
#pragma unroll
                for (int v = 0; v < 8; v++) acc[u][v] += a[u] * bv[v];
        }
        if (nn < NNODE) {
            int nx = cur ^ 1;
            *(float4*)&As[nx][lk0][lj0] = pa0;
            *(float4*)&As[nx][lk1][lj1] = pa1;
            *(float4*)&Bs[nx][lk0][lj0] = pb0;
            *(float4*)&Bs[nx][lk1][lj1] = pb1;
            __syncthreads();
            cur = nx;
        }
    }
#pragma unroll
    for (int u = 0; u < 8; u++) {
        int row = ty * 8 + u;
        *(float4*)&C[(size_t)row * KAP + tx * 8] =
            make_float4(acc[u][0], acc[u][1], acc[u][2], acc[u][3]);
        *(float4*)&C[(size_t)row * KAP + tx * 8 + 4] =
            make_float4(acc[u][4], acc[u][5], acc[u][6], acc[u][7]);
    }
}

// ---------------------------------------------------------------------------
__global__ __launch_bounds__(256) void atb8_32_kernel(const float* __restrict__ s1p,
                                                      const float* __restrict__ h,
                                                      float* __restrict__ x1) {
    __shared__ float As[16][128];
    __shared__ float Bs[16][32];
    int b = blockIdx.x;
    const float* A = s1p + ((size_t)b << 9) * KAP;
    const float* B = h + ((size_t)b << 9) * HID;
    float* C = x1 + (size_t)b * KA * HID;
    int tid = threadIdx.x;
    int tx = tid & 7, ty = tid >> 3;
    float acc[4][4] = {};
    for (int n0 = 0; n0 < NNODE; n0 += 16) {
#pragma unroll
        for (int r = 0; r < 2; r++) {
            int t4 = tid + r * 256;
            int kk = t4 >> 5, jf = (t4 & 31) << 2;
            *(float4*)&As[kk][jf] = *(const float4*)(A + (n0 + kk) * KAP + jf);
        }
        if (tid < 128) {
            int kk = tid >> 3, jf = (tid & 7) << 2;
            *(float4*)&Bs[kk][jf] = *(const float4*)(B + (n0 + kk) * HID + jf);
        }
        __syncthreads();
#pragma unroll
        for (int kk = 0; kk < 16; kk++) {
            float4 av = *(float4*)&As[kk][ty * 4];
            float4 bb = *(float4*)&Bs[kk][tx * 4];
            float a[4] = {av.x, av.y, av.z, av.w};
            float bv[4] = {bb.x, bb.y, bb.z, bb.w};
#pragma unroll
            for (int u = 0; u < 4; u++)
#pragma unroll
                for (int v = 0; v < 4; v++) acc[u][v] += a[u] * bv[v];
        }
        __syncthreads();
    }
#pragma unroll
    for (int u = 0; u < 4; u++) {
        int row = ty * 4 + u;
        if (row < KA)
            *(float4*)&C[(size_t)row * HID + tx * 4] =
                make_float4(acc[u][0], acc[u][1], acc[u][2], acc[u][3]);
    }
}

// ---------------------------------------------------------------------------
__global__ __launch_bounds__(256) void pool_softmax1_kernel(
    const float* __restrict__ X, const float* __restrict__ W,
    const float* __restrict__ bias, float* __restrict__ Sout) {
    __shared__ float Ws[HID * KAP];
    __shared__ float bs[KAP];
    int tid = threadIdx.x;
    for (int t = tid; t < HID * KAP; t += 256) {
        int c = t >> 7, k = t & 127;
        Ws[t] = (k < KA) ? W[c * KA + k] : 0.f;
    }
    if (tid < KAP) bs[tid] = (tid < KA) ? bias[tid] : 0.f;
    __syncthreads();
    int lane = tid & 31, warp = tid >> 5;
    int row0 = blockIdx.x * 64 + warp * 8;
#pragma unroll
    for (int r = 0; r < 8; r++) {
        int row = row0 + r;
        float xv = X[(size_t)row * HID + lane];
        float a0 = bs[lane], a1 = bs[32 + lane], a2 = bs[64 + lane], a3 = bs[96 + lane];
#pragma unroll
        for (int c = 0; c < HID; c++) {
            float bx = __shfl_sync(0xffffffffu, xv, c);
            const float* wr = Ws + (c << 7) + lane;
            a0 += bx * wr[0];
            a1 += bx * wr[32];
            a2 += bx * wr[64];
            a3 += bx * wr[96];
        }
        float e0 = __expf(a0), e1 = __expf(a1), e2 = __expf(a2);
        float e3 = (96 + lane < KA) ? __expf(a3) : 0.f;
        float s = (e0 + e1) + (e2 + e3);
#pragma unroll
        for (int o = 16; o; o >>= 1) s += __shfl_xor_sync(0xffffffffu, s, o);
        float inv = __frcp_rn(s);
        float* op = Sout + (size_t)row * KAP + lane;
        op[0]  = e0 * inv;
        op[32] = e1 * inv;
        op[64] = e2 * inv;
        op[96] = e3 * inv;
    }
}

// ---------------------------------------------------------------------------
__device__ __forceinline__ float blockReduce128(float v, float* sm) {
    int t = threadIdx.x;
    sm[t] = v;
    __syncthreads();
    for (int s = 64; s > 0; s >>= 1) {
        if (t < s) sm[t] += sm[t + s];
        __syncthreads();
    }
    float r = sm[0];
    __syncthreads();
    return r;
}

__global__ void loss_norm_kernel(const float* __restrict__ raw,
                                 const float* __restrict__ ss,
                                 const float* __restrict__ s,
                                 const float* __restrict__ dflat,
                                 float* __restrict__ adjn,
                                 float* __restrict__ dflat2,
                                 float* __restrict__ lossb,
                                 int k, int n, int ld, int ld_s, int bstride,
                                 int accum) {
    int b = blockIdx.x;
    raw  += (size_t)b * bstride;
    ss   += (size_t)b * bstride;
    s    += (size_t)b * n * ld_s;
    dflat+= (size_t)b * n;
    adjn += (size_t)b * k * k;
    dflat2 += (size_t)b * k;
    __shared__ float sm[128];
    __shared__ float idc[128];
    int tid = threadIdx.x;

    float v = 0.f;
    for (int i = tid; i < k; i += 128) v += raw[i * ld + i];
    float num = blockReduce128(v, sm);

    v = 0.f;
    for (int nn = tid; nn < n; nn += 128) {
        float dv = dflat[nn];
        float acc = 0.f;
        for (int kk = 0; kk < k; kk++) {
            float sv = s[(size_t)nn * ld_s + kk];
            acc += sv * sv;
        }
        v += acc * dv;
    }
    float den = blockReduce128(v, sm);

    v = 0.f;
    for (int i = tid; i < k; i += 128)
        for (int j = 0; j < k; j++) { float t = ss[i * ld + j]; v += t * t; }
    float nrm = sqrtf(blockReduce128(v, sm));

    float invn = 1.0f / nrm;
    float dk = rsqrtf((float)k);
    v = 0.f;
    for (int i = tid; i < k; i += 128)
        for (int j = 0; j < k; j++) {
            float t = ss[i * ld + j] * invn - ((i == j) ? dk : 0.f);
            v += t * t;
        }
    float ortho = sqrtf(blockReduce128(v, sm));

    for (int i = tid; i < k; i += 128) {
        float r = 0.f;
        for (int j = 0; j < k; j++) if (j != i) r += raw[i * ld + j];
        idc[i] = 1.0f / (sqrtf(r) + EPSV);
    }
    __syncthreads();
    for (int idx = tid; idx < k * k; idx += 128) {
        int i = idx / k, j = idx - i * k;
        adjn[idx] = (i == j) ? 0.f : raw[i * ld + j] * idc[i] * idc[j];
    }
    for (int i = tid; i < k; i += 128) {
        float r = 0.f;
        for (int j = 0; j < k; j++) if (j != i) r += raw[i * ld + j] * idc[j];
        dflat2[i] = r * idc[i];
    }
    if (tid == 0) {
        float val = -num / den + ortho;
        if (accum) lossb[b] += val; else lossb[b] = val;
    }
}

// ---------------------------------------------------------------------------
__global__ __launch_bounds__(256) void stage2_conv_kernel(
    const float* __restrict__ adj1, const float* __restrict__ x1,
    const float* __restrict__ relW, const float* __restrict__ relb,
    const float* __restrict__ rootW,
    const float* __restrict__ p2W, const float* __restrict__ p2b,
    float* __restrict__ x2, float* __restrict__ s2) {
    extern __shared__ float sm[];
    float* adj1s = sm;
    float* x1s   = sm + 10000;
    float* relWs = sm + 13200;
    float* rootWs= sm + 14224;
    float* p2Ws  = sm + 15248;
    int b = blockIdx.x, tid = threadIdx.x;
    const float* A = adj1 + (size_t)b * KA * KA;
    const float* X = x1 + (size_t)b * KA * HID;
    for (int i = tid; i < KA * KA; i += 256) adj1s[i] = A[i];
    for (int i = tid; i < KA * HID; i += 256) x1s[i] = X[i];
    for (int i = tid; i < HID * HID; i += 256) { relWs[i] = relW[i]; rootWs[i] = rootW[i]; }
    for (int i = tid; i < HID * KB; i += 256) p2Ws[i] = p2W[i];
    __syncthreads();
    int lane = tid & 31, warp = tid >> 5;
    float rb = relb[lane];
    int kk10 = lane < KB ? lane : 0;
    float p2bv = p2b[kk10];
    for (int i = warp; i < KA; i += 8) {
        float t2 = 0.f;
        const float* ar = adj1s + i * KA;
        for (int m = 0; m < KA; m++) t2 += ar[m] * x1s[(m << 5) + lane];
        float x1v = x1s[(i << 5) + lane];
        float a = rb;
#pragma unroll
        for (int k = 0; k < 32; k++)
            a += __shfl_sync(0xffffffffu, t2, k) * relWs[(k << 5) + lane]
               + __shfl_sync(0xffffffffu, x1v, k) * rootWs[(k << 5) + lane];
        float x2v = fmaxf(a, 0.f);
        x2[((size_t)b * KA + i) * HID + lane] = x2v;
        float zz = p2bv;
#pragma unroll
        for (int c = 0; c < 32; c++)
            zz += __shfl_sync(0xffffffffu, x2v, c) * p2Ws[c * KB + kk10];
        float e = (lane < KB) ? __expf(zz) : 0.f;
        float ssum = e;
#pragma unroll
        for (int o = 16; o; o >>= 1) ssum += __shfl_xor_sync(0xffffffffu, ssum, o);
        if (lane < KB) s2[((size_t)b * KA + i) * KB + lane] = e / ssum;
    }
}

// ---------------------------------------------------------------------------
__global__ __launch_bounds__(256) void stage2b_kernel(
    const float* __restrict__ adj1, const float* __restrict__ s2,
    const float* __restrict__ x2,
    float* __restrict__ adjr2, float* __restrict__ ss2, float* __restrict__ x3) {
    extern __shared__ float sm[];
    float* adj1s = sm;
    float* s2s   = sm + 10000;
    float* x2s   = sm + 11000;
    float* tt2s  = sm + 14200;
    int b = blockIdx.x, tid = threadIdx.x;
    const float* A = adj1 + (size_t)b * KA * KA;
    const float* S2 = s2 + (size_t)b * KA * KB;
    const float* X2 = x2 + (size_t)b * KA * HID;
    for (int i = tid; i < KA * KA; i += 256) adj1s[i] = A[i];
    for (int i = tid; i < KA * KB; i += 256) s2s[i] = S2[i];
    for (int i = tid; i < KA * HID; i += 256) x2s[i] = X2[i];
    __syncthreads();
    for (int t = tid; t < KA * KB; t += 256) {
        int i = t / KB, k = t - i * KB;
        float a = 0.f;
        const float* ar = adj1s + i * KA;
        for (int m = 0; m < KA; m++) a += ar[m] * s2s[m * KB + k];
        tt2s[t] = a;
    }
    __syncthreads();
    for (int t = tid; t < 520; t += 256) {
        if (t < 100) {
            int i = t / 10, j = t - i * 10;
            float a = 0.f;
            for (int n = 0; n < KA; n++) a += s2s[n * KB + i] * tt2s[n * KB + j];
            adjr2[(size_t)b * 100 + t] = a;
        } else if (t < 200) {
            int u = t - 100;
            int i = u / 10, j = u - i * 10;
            float a = 0.f;
            for (int n = 0; n < KA; n++) a += s2s[n * KB + i] * s2s[n * KB + j];
            ss2[(size_t)b * 100 + u] = a;
        } else {
            int u = t - 200;
            int i = u >> 5, c = u & 31;
            float a = 0.f;
            for (int n = 0; n < KA; n++) a += s2s[n * KB + i] * x2s[(n << 5) + c];
            x3[(size_t)b * 320 + u] = a;
        }
    }
}

// ---------------------------------------------------------------------------
__global__ void tail_kernel(const float* __restrict__ adj2, const float* __restrict__ x3,
                            const float* __restrict__ c3rW, const float* __restrict__ c3rb,
                            const float* __restrict__ c3oW,
                            const float* __restrict__ l1W, const float* __restrict__ l1b,
                            const float* __restrict__ l2W, const float* __restrict__ l2b,
                            float* __restrict__ out) {
    int b = blockIdx.x, lane = threadIdx.x;
    const float* A2 = adj2 + (size_t)b * 100;
    const float* X3 = x3 + (size_t)b * 320;
    float x3c[10], t3c[10];
#pragma unroll
    for (int j = 0; j < 10; j++) x3c[j] = X3[j * 32 + lane];
#pragma unroll
    for (int i = 0; i < 10; i++) {
        float a = 0.f;
#pragma unroll
        for (int j = 0; j < 10; j++) a += A2[i * 10 + j] * x3c[j];
        t3c[i] = a;
    }
    float rb = c3rb[lane];
    float g = 0.f;
#pragma unroll
    for (int i = 0; i < 10; i++) {
        float a = rb;
#pragma unroll
        for (int k = 0; k < 32; k++)
            a += __shfl_sync(0xffffffffu, t3c[i], k) * c3rW[k * 32 + lane]
               + __shfl_sync(0xffffffffu, x3c[i], k) * c3oW[k * 32 + lane];
        g += a;
    }
    g *= 0.1f;
    float a1 = l1b[lane];
#pragma unroll
    for (int k = 0; k < 32; k++) a1 += __shfl_sync(0xffffffffu, g, k) * l1W[k * 32 + lane];
    float gg = fmaxf(a1, 0.f);
    int kk = lane < OC ? lane : 0;
    float a2 = l2b[kk];
#pragma unroll
    for (int k = 0; k < 32; k++) a2 += __shfl_sync(0xffffffffu, gg, k) * l2W[k * OC + kk];
    float val = (lane < OC) ? a2 : -INFINITY;
    float m = val;
#pragma unroll
    for (int o = 16; o; o >>= 1) m = fmaxf(m, __shfl_xor_sync(0xffffffffu, m, o));
    float e = (lane < OC) ? __expf(val - m) : 0.f;
    float ssum = e;
#pragma unroll
    for (int o = 16; o; o >>= 1) ssum += __shfl_xor_sync(0xffffffffu, ssum, o);
    if (lane < OC) out[b * OC + lane] = val - m - logf(ssum);
}

__global__ void final_kernel(const float* __restrict__ lossb, float* __restrict__ out,
                             int out_size) {
    __shared__ float sm[128];
    int t = threadIdx.x;
    sm[t] = lossb[t];
    __syncthreads();
    for (int s = 64; s > 0; s >>= 1) {
        if (t < s) sm[t] += sm[t + s];
        __syncthreads();
    }
    if (t == 0 && out_size > BATCH * OC) out[BATCH * OC] = sm[0] / (float)BATCH;
}

// ---------------------------------------------------------------------------
extern "C" void kernel_launch(void* const* d_in, const int* in_sizes, int n_in,
                              void* d_out, int out_size) {
    const float* x    = (const float*)d_in[0];
    const int*   ei   = (const int*)  d_in[1];
    const float* c1W  = (const float*)d_in[3];
    const float* c1b  = (const float*)d_in[4];
    const float* p1W  = (const float*)d_in[5];
    const float* p1b  = (const float*)d_in[6];
    const float* c2rW = (const float*)d_in[7];
    const float* c2rb = (const float*)d_in[8];
    const float* c2oW = (const float*)d_in[9];
    const float* p2W  = (const float*)d_in[10];
    const float* p2b  = (const float*)d_in[11];
    const float* c3rW = (const float*)d_in[12];
    const float* c3rb = (const float*)d_in[13];
    const float* c3oW = (const float*)d_in[14];
    const float* l1W  = (const float*)d_in[15];
    const float* l1b  = (const float*)d_in[16];
    const float* l2W  = (const float*)d_in[17];
    const float* l2b  = (const float*)d_in[18];
    float* out = (float*)d_out;
    int E = in_sizes[1] / 2;
    int eper = E / BATCH;

    void* sp = nullptr;
    cudaGetSymbolAddress(&sp, g_scratch);
    float* S = (float*)sp;
    int *csn, *cdn, *osn, *odn, *lsrc, *ldst;
    cudaGetSymbolAddress((void**)&csn, g_cnt_src);
    cudaGetSymbolAddress((void**)&cdn, g_cnt_dst);
    cudaGetSymbolAddress((void**)&osn, g_off_src);
    cudaGetSymbolAddress((void**)&odn, g_off_dst);
    cudaGetSymbolAddress((void**)&lsrc, g_list_src);
    cudaGetSymbolAddress((void**)&ldst, g_list_dst);

    cudaFuncSetAttribute(agg_smem_kernel, cudaFuncAttributeMaxDynamicSharedMemorySize, 65536);
    cudaFuncSetAttribute(t1_smem_kernel, cudaFuncAttributeMaxDynamicSharedMemorySize, 65536);
    cudaFuncSetAttribute(stage2_conv_kernel, cudaFuncAttributeMaxDynamicSharedMemorySize, 62272);
    cudaFuncSetAttribute(stage2b_kernel, cudaFuncAttributeMaxDynamicSharedMemorySize, 60800);

    build_csr_kernel<<<BATCH, 512>>>(ei, E, eper, osn, csn, odn, cdn, lsrc, ldst,
                                     S + OFF_DEG, S + OFF_DFLAT);
    xwp_kernel<<<TOT / 8, dim3(32, 8)>>>(x, c1W, S + OFF_DEG, S + OFF_XWP);
    agg_smem_kernel<<<BATCH, 512, 65536>>>(odn, cdn, ldst, S + OFF_XWP,
                                           S + OFF_DEG, c1b, S + OFF_H);
    pool_softmax1_kernel<<<TOT / 64, 256>>>(S + OFF_H, p1W, p1b, S + OFF_S1);
    { dim3 g(4, BATCH); t1_smem_kernel<<<g, 512, 65536>>>(osn, csn, lsrc, S + OFF_S1, S + OFF_T1); }
    { dim3 g(2, BATCH); atb8_128_kernel<<<g, 256>>>(S + OFF_S1, S + OFF_T1, S + OFF_ADJR1, S + OFF_SS1); }
    atb8_32_kernel<<<BATCH, 256>>>(S + OFF_S1, S + OFF_H, S + OFF_X1);
    loss_norm_kernel<<<BATCH, 128>>>(S + OFF_ADJR1, S + OFF_SS1, S + OFF_S1, S + OFF_DFLAT,
                                     S + OFF_ADJ1, S + OFF_DFLAT2, S + OFF_LOSSB,
                                     KA, NNODE, KAP, KAP, KAP * KAP, 0);
    stage2_conv_kernel<<<BATCH, 256, 62272>>>(S + OFF_ADJ1, S + OFF_X1, c2rW, c2rb, c2oW,
                                              p2W, p2b, S + OFF_X2, S + OFF_S2);
    stage2b_kernel<<<BATCH, 256, 60800>>>(S + OFF_ADJ1, S + OFF_S2, S + OFF_X2,
                                          S + OFF_ADJR2, S + OFF_SS2, S + OFF_X3);
    loss_norm_kernel<<<BATCH, 128>>>(S + OFF_ADJR2, S + OFF_SS2, S + OFF_S2, S + OFF_DFLAT2,
                                     S + OFF_ADJ2, S + OFF_DUMMY, S + OFF_LOSSB,
                                     KB, KA, KB, KB, KB * KB, 1);
    tail_kernel<<<BATCH, 32>>>(S + OFF_ADJ2, S + OFF_X3, c3rW, c3rb, c3oW,
                               l1W, l1b, l2W, l2b, out);
    final_kernel<<<1, 128>>>(S + OFF_LOSSB, out, out_size);
}

// round 7
// speedup vs baseline: 1.1238x; 1.1238x over previous
#include <cuda_runtime.h>
#include <math.h>

namespace {
constexpr int BATCH = 128, NNODE = 512, INC = 128, HID = 32, KA = 100, KB = 10, OC = 10;
constexpr int KAP = 128;
constexpr int TOT = BATCH * NNODE;
constexpr int MAXE = BATCH * 8192;
constexpr float EPSV = 1e-15f;

constexpr size_t OFF_DEG    = 0;
constexpr size_t OFF_DFLAT  = OFF_DEG + TOT;
constexpr size_t OFF_LOSSB  = OFF_DFLAT + TOT;
constexpr size_t OFF_XWP    = OFF_LOSSB + BATCH;
constexpr size_t OFF_H      = OFF_XWP   + (size_t)TOT * HID;
constexpr size_t OFF_S1     = OFF_H     + (size_t)TOT * HID;
constexpr size_t OFF_T1     = OFF_S1    + (size_t)TOT * KAP;
constexpr size_t OFF_ADJR1  = OFF_T1    + (size_t)TOT * KAP;
constexpr size_t OFF_SS1    = OFF_ADJR1 + (size_t)BATCH * KAP * KAP;
constexpr size_t OFF_X1     = OFF_SS1   + (size_t)BATCH * KAP * KAP;
constexpr size_t OFF_ADJ1   = OFF_X1    + (size_t)BATCH * KA * HID;
constexpr size_t OFF_DFLAT2 = OFF_ADJ1  + (size_t)BATCH * KA * KA;
constexpr size_t OFF_DUMMY  = OFF_DFLAT2+ (size_t)BATCH * KA;
constexpr size_t OFF_X2     = OFF_DUMMY + (size_t)BATCH * KB;
constexpr size_t OFF_S2     = OFF_X2    + (size_t)BATCH * KA * HID;
constexpr size_t OFF_ADJR2  = OFF_S2    + (size_t)BATCH * KA * KB;
constexpr size_t OFF_SS2    = OFF_ADJR2 + (size_t)BATCH * KB * KB;
constexpr size_t OFF_X3     = OFF_SS2   + (size_t)BATCH * KB * KB;
constexpr size_t OFF_ADJ2   = OFF_X3    + (size_t)BATCH * KB * HID;
constexpr size_t SCRATCH_TOTAL = OFF_ADJ2 + (size_t)BATCH * KB * KB;
}  // namespace

__device__ __align__(16) float g_scratch[SCRATCH_TOTAL];
__device__ __align__(16) int g_cnt_src[TOT];
__device__ __align__(16) int g_cnt_dst[TOT];
__device__ __align__(16) int g_off_src[TOT];
__device__ __align__(16) int g_off_dst[TOT];
__device__ __align__(16) int g_list_src[MAXE];   // dst-locals grouped by src
__device__ __align__(16) int g_list_dst[MAXE];   // src-locals grouped by dst

// ---------------------------------------------------------------------------
// Fused CSR build: one block per graph. smem count -> scan -> smem-cursor fill.
// ---------------------------------------------------------------------------
__global__ __launch_bounds__(512) void build_csr_kernel(
    const int* __restrict__ ei, int E, int eper,
    int* __restrict__ off_src, int* __restrict__ cnt_src,
    int* __restrict__ off_dst, int* __restrict__ cnt_dst,
    int* __restrict__ list_src, int* __restrict__ list_dst,
    float* __restrict__ deg, float* __restrict__ dflat) {
    __shared__ int sc[512], sd[512], sscan[512];
    __shared__ int csrc[512], cdst[512];
    int b = blockIdx.x, tid = threadIdx.x;
    sc[tid] = 0; sd[tid] = 0;
    __syncthreads();
    const int* se = ei + (size_t)b * eper;
    const int* de = ei + E + (size_t)b * eper;
    for (int e = tid; e < eper; e += 512) {
        atomicAdd(&sc[se[e] & 511], 1);
        atomicAdd(&sd[de[e] & 511], 1);
    }
    __syncthreads();
    int vs = sc[tid], vd = sd[tid];
    int g = (b << 9) + tid;
    int base = b * eper;
    dflat[g] = (float)vs;
    deg[g]   = (float)vd;
    cnt_src[g] = vs;
    cnt_dst[g] = vd;
    sscan[tid] = vs; __syncthreads();
    for (int o = 1; o < 512; o <<= 1) {
        int t = (tid >= o) ? sscan[tid - o] : 0;
        __syncthreads(); sscan[tid] += t; __syncthreads();
    }
    int es = base + sscan[tid] - vs;
    off_src[g] = es; csrc[tid] = es;
    __syncthreads();
    sscan[tid] = vd; __syncthreads();
    for (int o = 1; o < 512; o <<= 1) {
        int t = (tid >= o) ? sscan[tid - o] : 0;
        __syncthreads(); sscan[tid] += t; __syncthreads();
    }
    int ed = base + sscan[tid] - vd;
    off_dst[g] = ed; cdst[tid] = ed;
    __syncthreads();
    for (int e = tid; e < eper; e += 512) {
        int s = se[e] & 511, d = de[e] & 511;
        int p = atomicAdd(&csrc[s], 1);
        list_src[p] = d;
        int q = atomicAdd(&cdst[d], 1);
        list_dst[q] = s;
    }
}

// ---------------------------------------------------------------------------
__global__ __launch_bounds__(256) void xwp_kernel(const float* __restrict__ x,
                                                  const float* __restrict__ W,
                                                  const float* __restrict__ deg,
                                                  float* __restrict__ xwp) {
    __shared__ float Ws[INC * HID];
    __shared__ float xs[8][INC];
    int tid = threadIdx.y * 32 + threadIdx.x;
    for (int t = tid; t < INC * HID; t += 256) Ws[t] = W[t];
    int r0 = blockIdx.x * 8;
    for (int t = tid; t < 8 * INC; t += 256) {
        int r = t >> 7, k = t & 127;
        xs[r][k] = x[(size_t)(r0 + r) * INC + k];
    }
    __syncthreads();
    int c = threadIdx.x, r = threadIdx.y;
    float acc = 0.f;
#pragma unroll 8
    for (int k = 0; k < INC; k++) acc += xs[r][k] * Ws[k * HID + c];
    int g = r0 + r;
    float dis = rsqrtf(deg[g] + 1.0f);
    xwp[(size_t)g * HID + c] = dis * acc;
}

// ---------------------------------------------------------------------------
// GCN aggregate via L2 gather: one warp per dest node; lane = column.
// ---------------------------------------------------------------------------
__global__ __launch_bounds__(256) void agg_gather_kernel(
    const int* __restrict__ off_dst, const int* __restrict__ cnt_dst,
    const int* __restrict__ list_dst,
    const float* __restrict__ xwp, const float* __restrict__ deg,
    const float* __restrict__ bias, float* __restrict__ h) {
    int node = (blockIdx.x * blockDim.x + threadIdx.x) >> 5;
    int lane = threadIdx.x & 31;
    if (node >= TOT) return;
    int b = node >> 9;
    const float* xb = xwp + (((size_t)b << 9) << 5);
    int off = off_dst[node], cnt = cnt_dst[node];
    float acc = 0.f;
    int i = off, end = off + cnt;
    for (; i + 3 < end; i += 4) {
        int s0 = __ldg(&list_dst[i]),   s1 = __ldg(&list_dst[i + 1]);
        int s2 = __ldg(&list_dst[i + 2]), s3 = __ldg(&list_dst[i + 3]);
        acc += xb[(s0 << 5) + lane] + xb[(s1 << 5) + lane]
             + xb[(s2 << 5) + lane] + xb[(s3 << 5) + lane];
    }
    for (; i < end; i++) acc += xb[(__ldg(&list_dst[i]) << 5) + lane];
    float dis = rsqrtf(deg[node] + 1.0f);
    float xv = xwp[((size_t)node << 5) + lane];
    h[((size_t)node << 5) + lane] = fmaxf(dis * (acc + xv) + bias[lane], 0.f);
}

// ---------------------------------------------------------------------------
// T1 = A @ s1 via L2 gather: one warp per source node; lane = float4 chunk.
// ---------------------------------------------------------------------------
__global__ __launch_bounds__(256) void t1_gather_kernel(
    const int* __restrict__ off_src, const int* __restrict__ cnt_src,
    const int* __restrict__ list_src,
    const float* __restrict__ s1p, float* __restrict__ T1) {
    int node = (blockIdx.x * blockDim.x + threadIdx.x) >> 5;
    int lane = threadIdx.x & 31;
    if (node >= TOT) return;
    int b = node >> 9;
    const float4* sb = (const float4*)(s1p + (((size_t)b << 9) << 7)) + lane;
    int off = off_src[node], cnt = cnt_src[node];
    float4 acc = make_float4(0, 0, 0, 0);
    int i = off, end = off + cnt;
    for (; i + 3 < end; i += 4) {
        int d0 = __ldg(&list_src[i]),     d1 = __ldg(&list_src[i + 1]);
        int d2 = __ldg(&list_src[i + 2]), d3 = __ldg(&list_src[i + 3]);
        float4 v0 = __ldg(&sb[d0 << 5]);
        float4 v1 = __ldg(&sb[d1 << 5]);
        float4 v2 = __ldg(&sb[d2 << 5]);
        float4 v3 = __ldg(&sb[d3 << 5]);
        acc.x += (v0.x + v1.x) + (v2.x + v3.x);
        acc.y += (v0.y + v1.y) + (v2.y + v3.y);
        acc.z += (v0.z + v1.z) + (v2.z + v3.z);
        acc.w += (v0.w + v1.w) + (v2.w + v3.w);
    }
    for (; i < end; i++) {
        float4 v = __ldg(&sb[__ldg(&list_src[i]) << 5]);
        acc.x += v.x; acc.y += v.y; acc.z += v.z; acc.w += v.w;
    }
    ((float4*)(T1 + ((size_t)node << 7)))[lane] = acc;
}

// ---------------------------------------------------------------------------
// adjr1 = s1^T T1 (sel=0) / ss1 = s1^T s1 (sel=1). Double-buffered, micro 8x8.
// ---------------------------------------------------------------------------
__global__ __launch_bounds__(256) void atb8_128_kernel(const float* __restrict__ s1p,
                                                       const float* __restrict__ T1,
                                                       float* __restrict__ adjr1,
                                                       float* __restrict__ ss1) {
    __shared__ float As[2][16][128];
    __shared__ float Bs[2][16][128];
    int b = blockIdx.y;
    int sel = blockIdx.x;
    const float* A = s1p + ((size_t)b << 9) * KAP;
    const float* B = (sel ? s1p : T1) + ((size_t)b << 9) * KAP;
    float* C = (sel ? ss1 : adjr1) + (size_t)b * KAP * KAP;
    int tid = threadIdx.x;
    int tx = tid & 15, ty = tid >> 4;
    int lk0 = tid >> 5,         lj0 = (tid & 31) << 2;
    int lk1 = (tid + 256) >> 5, lj1 = ((tid + 256) & 31) << 2;

    float4 pa0, pa1, pb0, pb1;
    pa0 = *(const float4*)(A + lk0 * KAP + lj0);
    pa1 = *(const float4*)(A + lk1 * KAP + lj1);
    pb0 = *(const float4*)(B + lk0 * KAP + lj0);
    pb1 = *(const float4*)(B + lk1 * KAP + lj1);
    *(float4*)&As[0][lk0][lj0] = pa0;
    *(float4*)&As[0][lk1][lj1] = pa1;
    *(float4*)&Bs[0][lk0][lj0] = pb0;
    *(float4*)&Bs[0][lk1][lj1] = pb1;
    __syncthreads();

    float acc[8][8] = {};
    int cur = 0;
    for (int n0 = 0; n0 < NNODE; n0 += 16) {
        int nn = n0 + 16;
        if (nn < NNODE) {
            pa0 = *(const float4*)(A + (nn + lk0) * KAP + lj0);
            pa1 = *(const float4*)(A + (nn + lk1) * KAP + lj1);
            pb0 = *(const float4*)(B + (nn + lk0) * KAP + lj0);
            pb1 = *(const float4*)(B + (nn + lk1) * KAP + lj1);
        }
#pragma unroll
        for (int kk = 0; kk < 16; kk++) {
            float4 a0 = *(float4*)&As[cur][kk][ty * 8];
            float4 a1 = *(float4*)&As[cur][kk][ty * 8 + 4];
            float4 b0 = *(float4*)&Bs[cur][kk][tx * 8];
            float4 b1 = *(float4*)&Bs[cur][kk][tx * 8 + 4];
            float a[8] = {a0.x, a0.y, a0.z, a0.w, a1.x, a1.y, a1.z, a1.w};
            float bv[8] = {b0.x, b0.y, b0.z, b0.w, b1.x, b1.y, b1.z, b1.w};
#pragma unroll
            for (int u = 0; u < 8; u++)
#pragma unroll
                for (int v = 0; v < 8; v++) acc[u][v] += a[u] * bv[v];
        }
        if (nn < NNODE) {
            int nx = cur ^ 1;
            *(float4*)&As[nx][lk0][lj0] = pa0;
            *(float4*)&As[nx][lk1][lj1] = pa1;
            *(float4*)&Bs[nx][lk0][lj0] = pb0;
            *(float4*)&Bs[nx][lk1][lj1] = pb1;
            __syncthreads();
            cur = nx;
        }
    }
#pragma unroll
    for (int u = 0; u < 8; u++) {
        int row = ty * 8 + u;
        *(float4*)&C[(size_t)row * KAP + tx * 8] =
            make_float4(acc[u][0], acc[u][1], acc[u][2], acc[u][3]);
        *(float4*)&C[(size_t)row * KAP + tx * 8 + 4] =
            make_float4(acc[u][4], acc[u][5], acc[u][6], acc[u][7]);
    }
}

// ---------------------------------------------------------------------------
__global__ __launch_bounds__(256) void atb8_32_kernel(const float* __restrict__ s1p,
                                                      const float* __restrict__ h,
                                                      float* __restrict__ x1) {
    __shared__ float As[16][128];
    __shared__ float Bs[16][32];
    int b = blockIdx.x;
    const float* A = s1p + ((size_t)b << 9) * KAP;
    const float* B = h + ((size_t)b << 9) * HID;
    float* C = x1 + (size_t)b * KA * HID;
    int tid = threadIdx.x;
    int tx = tid & 7, ty = tid >> 3;
    float acc[4][4] = {};
    for (int n0 = 0; n0 < NNODE; n0 += 16) {
#pragma unroll
        for (int r = 0; r < 2; r++) {
            int t4 = tid + r * 256;
            int kk = t4 >> 5, jf = (t4 & 31) << 2;
            *(float4*)&As[kk][jf] = *(const float4*)(A + (n0 + kk) * KAP + jf);
        }
        if (tid < 128) {
            int kk = tid >> 3, jf = (tid & 7) << 2;
            *(float4*)&Bs[kk][jf] = *(const float4*)(B + (n0 + kk) * HID + jf);
        }
        __syncthreads();
#pragma unroll
        for (int kk = 0; kk < 16; kk++) {
            float4 av = *(float4*)&As[kk][ty * 4];
            float4 bb = *(float4*)&Bs[kk][tx * 4];
            float a[4] = {av.x, av.y, av.z, av.w};
            float bv[4] = {bb.x, bb.y, bb.z, bb.w};
#pragma unroll
            for (int u = 0; u < 4; u++)
#pragma unroll
                for (int v = 0; v < 4; v++) acc[u][v] += a[u] * bv[v];
        }
        __syncthreads();
    }
#pragma unroll
    for (int u = 0; u < 4; u++) {
        int row = ty * 4 + u;
        if (row < KA)
            *(float4*)&C[(size_t)row * HID + tx * 4] =
                make_float4(acc[u][0], acc[u][1], acc[u][2], acc[u][3]);
    }
}

// ---------------------------------------------------------------------------
// stage-1 pooled softmax. Row loop NOT unrolled: keeps one row's state live
// (~48 regs) so occupancy recovers.
// ---------------------------------------------------------------------------
__global__ __launch_bounds__(256) void pool_softmax1_kernel(
    const float* __restrict__ X, const float* __restrict__ W,
    const float* __restrict__ bias, float* __restrict__ Sout) {
    __shared__ float Ws[HID * KAP];
    __shared__ float bs[KAP];
    int tid = threadIdx.x;
    for (int t = tid; t < HID * KAP; t += 256) {
        int c = t >> 7, k = t & 127;
        Ws[t] = (k < KA) ? W[c * KA + k] : 0.f;
    }
    if (tid < KAP) bs[tid] = (tid < KA) ? bias[tid] : 0.f;
    __syncthreads();
    int lane = tid & 31, warp = tid >> 5;
    int row0 = blockIdx.x * 64 + warp * 8;
#pragma unroll 1
    for (int r = 0; r < 8; r++) {
        int row = row0 + r;
        float xv = X[(size_t)row * HID + lane];
        float a0 = bs[lane], a1 = bs[32 + lane], a2 = bs[64 + lane], a3 = bs[96 + lane];
#pragma unroll
        for (int c = 0; c < HID; c++) {
            float bx = __shfl_sync(0xffffffffu, xv, c);
            const float* wr = Ws + (c << 7) + lane;
            a0 += bx * wr[0];
            a1 += bx * wr[32];
            a2 += bx * wr[64];
            a3 += bx * wr[96];
        }
        float e0 = __expf(a0), e1 = __expf(a1), e2 = __expf(a2);
        float e3 = (96 + lane < KA) ? __expf(a3) : 0.f;
        float s = (e0 + e1) + (e2 + e3);
#pragma unroll
        for (int o = 16; o; o >>= 1) s += __shfl_xor_sync(0xffffffffu, s, o);
        float inv = __frcp_rn(s);
        float* op = Sout + (size_t)row * KAP + lane;
        op[0]  = e0 * inv;
        op[32] = e1 * inv;
        op[64] = e2 * inv;
        op[96] = e3 * inv;
    }
}

// ---------------------------------------------------------------------------
__device__ __forceinline__ float blockReduce128(float v, float* sm) {
    int t = threadIdx.x;
    sm[t] = v;
    __syncthreads();
    for (int s = 64; s > 0; s >>= 1) {
        if (t < s) sm[t] += sm[t + s];
        __syncthreads();
    }
    float r = sm[0];
    __syncthreads();
    return r;
}

__global__ void loss_norm_kernel(const float* __restrict__ raw,
                                 const float* __restrict__ ss,
                                 const float* __restrict__ s,
                                 const float* __restrict__ dflat,
                                 float* __restrict__ adjn,
                                 float* __restrict__ dflat2,
                                 float* __restrict__ lossb,
                                 int k, int n, int ld, int ld_s, int bstride,
                                 int accum) {
    int b = blockIdx.x;
    raw  += (size_t)b * bstride;
    ss   += (size_t)b * bstride;
    s    += (size_t)b * n * ld_s;
    dflat+= (size_t)b * n;
    adjn += (size_t)b * k * k;
    dflat2 += (size_t)b * k;
    __shared__ float sm[128];
    __shared__ float idc[128];
    int tid = threadIdx.x;

    float v = 0.f;
    for (int i = tid; i < k; i += 128) v += raw[i * ld + i];
    float num = blockReduce128(v, sm);

    v = 0.f;
    for (int nn = tid; nn < n; nn += 128) {
        float dv = dflat[nn];
        float acc = 0.f;
        for (int kk = 0; kk < k; kk++) {
            float sv = s[(size_t)nn * ld_s + kk];
            acc += sv * sv;
        }
        v += acc * dv;
    }
    float den = blockReduce128(v, sm);

    v = 0.f;
    for (int i = tid; i < k; i += 128)
        for (int j = 0; j < k; j++) { float t = ss[i * ld + j]; v += t * t; }
    float nrm = sqrtf(blockReduce128(v, sm));

    float invn = 1.0f / nrm;
    float dk = rsqrtf((float)k);
    v = 0.f;
    for (int i = tid; i < k; i += 128)
        for (int j = 0; j < k; j++) {
            float t = ss[i * ld + j] * invn - ((i == j) ? dk : 0.f);
            v += t * t;
        }
    float ortho = sqrtf(blockReduce128(v, sm));

    for (int i = tid; i < k; i += 128) {
        float r = 0.f;
        for (int j = 0; j < k; j++) if (j != i) r += raw[i * ld + j];
        idc[i] = 1.0f / (sqrtf(r) + EPSV);
    }
    __syncthreads();
    for (int idx = tid; idx < k * k; idx += 128) {
        int i = idx / k, j = idx - i * k;
        adjn[idx] = (i == j) ? 0.f : raw[i * ld + j] * idc[i] * idc[j];
    }
    for (int i = tid; i < k; i += 128) {
        float r = 0.f;
        for (int j = 0; j < k; j++) if (j != i) r += raw[i * ld + j] * idc[j];
        dflat2[i] = r * idc[i];
    }
    if (tid == 0) {
        float val = -num / den + ortho;
        if (accum) lossb[b] += val; else lossb[b] = val;
    }
}

// ---------------------------------------------------------------------------
__global__ __launch_bounds__(256) void stage2_conv_kernel(
    const float* __restrict__ adj1, const float* __restrict__ x1,
    const float* __restrict__ relW, const float* __restrict__ relb,
    const float* __restrict__ rootW,
    const float* __restrict__ p2W, const float* __restrict__ p2b,
    float* __restrict__ x2, float* __restrict__ s2) {
    extern __shared__ float sm[];
    float* adj1s = sm;
    float* x1s   = sm + 10000;
    float* relWs = sm + 13200;
    float* rootWs= sm + 14224;
    float* p2Ws  = sm + 15248;
    int b = blockIdx.x, tid = threadIdx.x;
    const float* A = adj1 + (size_t)b * KA * KA;
    const float* X = x1 + (size_t)b * KA * HID;
    for (int i = tid; i < KA * KA; i += 256) adj1s[i] = A[i];
    for (int i = tid; i < KA * HID; i += 256) x1s[i] = X[i];
    for (int i = tid; i < HID * HID; i += 256) { relWs[i] = relW[i]; rootWs[i] = rootW[i]; }
    for (int i = tid; i < HID * KB; i += 256) p2Ws[i] = p2W[i];
    __syncthreads();
    int lane = tid & 31, warp = tid >> 5;
    float rb = relb[lane];
    int kk10 = lane < KB ? lane : 0;
    float p2bv = p2b[kk10];
    for (int i = warp; i < KA; i += 8) {
        float t2 = 0.f;
        const float* ar = adj1s + i * KA;
        for (int m = 0; m < KA; m++) t2 += ar[m] * x1s[(m << 5) + lane];
        float x1v = x1s[(i << 5) + lane];
        float a = rb;
#pragma unroll
        for (int k = 0; k < 32; k++)
            a += __shfl_sync(0xffffffffu, t2, k) * relWs[(k << 5) + lane]
               + __shfl_sync(0xffffffffu, x1v, k) * rootWs[(k << 5) + lane];
        float x2v = fmaxf(a, 0.f);
        x2[((size_t)b * KA + i) * HID + lane] = x2v;
        float zz = p2bv;
#pragma unroll
        for (int c = 0; c < 32; c++)
            zz += __shfl_sync(0xffffffffu, x2v, c) * p2Ws[c * KB + kk10];
        float e = (lane < KB) ? __expf(zz) : 0.f;
        float ssum = e;
#pragma unroll
        for (int o = 16; o; o >>= 1) ssum += __shfl_xor_sync(0xffffffffu, ssum, o);
        if (lane < KB) s2[((size_t)b * KA + i) * KB + lane] = e / ssum;
    }
}

// ---------------------------------------------------------------------------
__global__ __launch_bounds__(256) void stage2b_kernel(
    const float* __restrict__ adj1, const float* __restrict__ s2,
    const float* __restrict__ x2,
    float* __restrict__ adjr2, float* __restrict__ ss2, float* __restrict__ x3) {
    extern __shared__ float sm[];
    float* adj1s = sm;
    float* s2s   = sm + 10000;
    float* x2s   = sm + 11000;
    float* tt2s  = sm + 14200;
    int b = blockIdx.x, tid = threadIdx.x;
    const float* A = adj1 + (size_t)b * KA * KA;
    const float* S2 = s2 + (size_t)b * KA * KB;
    const float* X2 = x2 + (size_t)b * KA * HID;
    for (int i = tid; i < KA * KA; i += 256) adj1s[i] = A[i];
    for (int i = tid; i < KA * KB; i += 256) s2s[i] = S2[i];
    for (int i = tid; i < KA * HID; i += 256) x2s[i] = X2[i];
    __syncthreads();
    for (int t = tid; t < KA * KB; t += 256) {
        int i = t / KB, k = t - i * KB;
        float a = 0.f;
        const float* ar = adj1s + i * KA;
        for (int m = 0; m < KA; m++) a += ar[m] * s2s[m * KB + k];
        tt2s[t] = a;
    }
    __syncthreads();
    for (int t = tid; t < 520; t += 256) {
        if (t < 100) {
            int i = t / 10, j = t - i * 10;
            float a = 0.f;
            for (int n = 0; n < KA; n++) a += s2s[n * KB + i] * tt2s[n * KB + j];
            adjr2[(size_t)b * 100 + t] = a;
        } else if (t < 200) {
            int u = t - 100;
            int i = u / 10, j = u - i * 10;
            float a = 0.f;
            for (int n = 0; n < KA; n++) a += s2s[n * KB + i] * s2s[n * KB + j];
            ss2[(size_t)b * 100 + u] = a;
        } else {
            int u = t - 200;
            int i = u >> 5, c = u & 31;
            float a = 0.f;
            for (int n = 0; n < KA; n++) a += s2s[n * KB + i] * x2s[(n << 5) + c];
            x3[(size_t)b * 320 + u] = a;
        }
    }
}

// ---------------------------------------------------------------------------
__global__ void tail_kernel(const float* __restrict__ adj2, const float* __restrict__ x3,
                            const float* __restrict__ c3rW, const float* __restrict__ c3rb,
                            const float* __restrict__ c3oW,
                            const float* __restrict__ l1W, const float* __restrict__ l1b,
                            const float* __restrict__ l2W, const float* __restrict__ l2b,
                            float* __restrict__ out) {
    int b = blockIdx.x, lane = threadIdx.x;
    const float* A2 = adj2 + (size_t)b * 100;
    const float* X3 = x3 + (size_t)b * 320;
    float x3c[10], t3c[10];
#pragma unroll
    for (int j = 0; j < 10; j++) x3c[j] = X3[j * 32 + lane];
#pragma unroll
    for (int i = 0; i < 10; i++) {
        float a = 0.f;
#pragma unroll
        for (int j = 0; j < 10; j++) a += A2[i * 10 + j] * x3c[j];
        t3c[i] = a;
    }
    float rb = c3rb[lane];
    float g = 0.f;
#pragma unroll
    for (int i = 0; i < 10; i++) {
        float a = rb;
#pragma unroll
        for (int k = 0; k < 32; k++)
            a += __shfl_sync(0xffffffffu, t3c[i], k) * c3rW[k * 32 + lane]
               + __shfl_sync(0xffffffffu, x3c[i], k) * c3oW[k * 32 + lane];
        g += a;
    }
    g *= 0.1f;
    float a1 = l1b[lane];
#pragma unroll
    for (int k = 0; k < 32; k++) a1 += __shfl_sync(0xffffffffu, g, k) * l1W[k * 32 + lane];
    float gg = fmaxf(a1, 0.f);
    int kk = lane < OC ? lane : 0;
    float a2 = l2b[kk];
#pragma unroll
    for (int k = 0; k < 32; k++) a2 += __shfl_sync(0xffffffffu, gg, k) * l2W[k * OC + kk];
    float val = (lane < OC) ? a2 : -INFINITY;
    float m = val;
#pragma unroll
    for (int o = 16; o; o >>= 1) m = fmaxf(m, __shfl_xor_sync(0xffffffffu, m, o));
    float e = (lane < OC) ? __expf(val - m) : 0.f;
    float ssum = e;
#pragma unroll
    for (int o = 16; o; o >>= 1) ssum += __shfl_xor_sync(0xffffffffu, ssum, o);
    if (lane < OC) out[b * OC + lane] = val - m - logf(ssum);
}

__global__ void final_kernel(const float* __restrict__ lossb, float* __restrict__ out,
                             int out_size) {
    __shared__ float sm[128];
    int t = threadIdx.x;
    sm[t] = lossb[t];
    __syncthreads();
    for (int s = 64; s > 0; s >>= 1) {
        if (t < s) sm[t] += sm[t + s];
        __syncthreads();
    }
    if (t == 0 && out_size > BATCH * OC) out[BATCH * OC] = sm[0] / (float)BATCH;
}

// ---------------------------------------------------------------------------
extern "C" void kernel_launch(void* const* d_in, const int* in_sizes, int n_in,
                              void* d_out, int out_size) {
    const float* x    = (const float*)d_in[0];
    const int*   ei   = (const int*)  d_in[1];
    const float* c1W  = (const float*)d_in[3];
    const float* c1b  = (const float*)d_in[4];
    const float* p1W  = (const float*)d_in[5];
    const float* p1b  = (const float*)d_in[6];
    const float* c2rW = (const float*)d_in[7];
    const float* c2rb = (const float*)d_in[8];
    const float* c2oW = (const float*)d_in[9];
    const float* p2W  = (const float*)d_in[10];
    const float* p2b  = (const float*)d_in[11];
    const float* c3rW = (const float*)d_in[12];
    const float* c3rb = (const float*)d_in[13];
    const float* c3oW = (const float*)d_in[14];
    const float* l1W  = (const float*)d_in[15];
    const float* l1b  = (const float*)d_in[16];
    const float* l2W  = (const float*)d_in[17];
    const float* l2b  = (const float*)d_in[18];
    float* out = (float*)d_out;
    int E = in_sizes[1] / 2;
    int eper = E / BATCH;

    void* sp = nullptr;
    cudaGetSymbolAddress(&sp, g_scratch);
    float* S = (float*)sp;
    int *csn, *cdn, *osn, *odn, *lsrc, *ldst;
    cudaGetSymbolAddress((void**)&csn, g_cnt_src);
    cudaGetSymbolAddress((void**)&cdn, g_cnt_dst);
    cudaGetSymbolAddress((void**)&osn, g_off_src);
    cudaGetSymbolAddress((void**)&odn, g_off_dst);
    cudaGetSymbolAddress((void**)&lsrc, g_list_src);
    cudaGetSymbolAddress((void**)&ldst, g_list_dst);

    cudaFuncSetAttribute(stage2_conv_kernel, cudaFuncAttributeMaxDynamicSharedMemorySize, 62272);
    cudaFuncSetAttribute(stage2b_kernel, cudaFuncAttributeMaxDynamicSharedMemorySize, 60800);

    build_csr_kernel<<<BATCH, 512>>>(ei, E, eper, osn, csn, odn, cdn, lsrc, ldst,
                                     S + OFF_DEG, S + OFF_DFLAT);
    xwp_kernel<<<TOT / 8, dim3(32, 8)>>>(x, c1W, S + OFF_DEG, S + OFF_XWP);
    agg_gather_kernel<<<TOT * 32 / 256, 256>>>(odn, cdn, ldst, S + OFF_XWP,
                                               S + OFF_DEG, c1b, S + OFF_H);
    pool_softmax1_kernel<<<TOT / 64, 256>>>(S + OFF_H, p1W, p1b, S + OFF_S1);
    t1_gather_kernel<<<TOT * 32 / 256, 256>>>(osn, csn, lsrc, S + OFF_S1, S + OFF_T1);
    { dim3 g(2, BATCH); atb8_128_kernel<<<g, 256>>>(S + OFF_S1, S + OFF_T1, S + OFF_ADJR1, S + OFF_SS1); }
    atb8_32_kernel<<<BATCH, 256>>>(S + OFF_S1, S + OFF_H, S + OFF_X1);
    loss_norm_kernel<<<BATCH, 128>>>(S + OFF_ADJR1, S + OFF_SS1, S + OFF_S1, S + OFF_DFLAT,
                                     S + OFF_ADJ1, S + OFF_DFLAT2, S + OFF_LOSSB,
                                     KA, NNODE, KAP, KAP, KAP * KAP, 0);
    stage2_conv_kernel<<<BATCH, 256, 62272>>>(S + OFF_ADJ1, S + OFF_X1, c2rW, c2rb, c2oW,
                                              p2W, p2b, S + OFF_X2, S + OFF_S2);
    stage2b_kernel<<<BATCH, 256, 60800>>>(S + OFF_ADJ1, S + OFF_S2, S + OFF_X2,
                                          S + OFF_ADJR2, S + OFF_SS2, S + OFF_X3);
    loss_norm_kernel<<<BATCH, 128>>>(S + OFF_ADJR2, S + OFF_SS2, S + OFF_S2, S + OFF_DFLAT2,
                                     S + OFF_ADJ2, S + OFF_DUMMY, S + OFF_LOSSB,
                                     KB, KA, KB, KB, KB * KB, 1);
    tail_kernel<<<BATCH, 32>>>(S + OFF_ADJ2, S + OFF_X3, c3rW, c3rb, c3oW,
                               l1W, l1b, l2W, l2b, out);
    final_kernel<<<1, 128>>>(S + OFF_LOSSB, out, out_size);
}